// round 12
// baseline (speedup 1.0000x reference)
#include <cuda_runtime.h>
#include <cuda_fp16.h>
#include <cstdint>
#include <cstddef>

#define NE    8
#define HID   2048
#define INTER 2816
#define NTOK  8192
#define CAP   8192             // cnt_e <= NTOK: a token routes to an expert at most once

// ---------------- scratch (device globals; no runtime allocation) ----------------
__device__ int    g_cursor[NE];
__device__ unsigned int g_wq;                  // work queue for idle gemm1 CTAs
__device__ int    g_list_c[NE * CAP];          // token*2 + slot
__device__ float  g_list_w[NE * CAP];
__device__ __half c_x[(size_t)NTOK * HID];             // fp16 x   (33 MB)
__device__ __half c_w13[(size_t)NE * 2 * INTER * HID]; // fp16 w13 (184 MB)
__device__ __half c_w2[(size_t)NE * HID * INTER];      // fp16 w2  (92 MB)
__device__ __half g_h[(size_t)NE * CAP * INTER];       // fp16 h   (369 MB)

// ---------------- helpers ----------------
__device__ __forceinline__ uint32_t smem_u32(const void* p) {
    uint32_t a;
    asm("{ .reg .u64 t; cvta.to.shared.u64 t, %1; cvt.u32.u64 %0, t; }" : "=r"(a) : "l"(p));
    return a;
}
__device__ __forceinline__ void cpasync16(uint32_t dst, const void* src, int srcsize) {
    asm volatile("cp.async.cg.shared.global [%0], [%1], 16, %2;"
                 :: "r"(dst), "l"(src), "r"(srcsize) : "memory");
}
#define CP_COMMIT() asm volatile("cp.async.commit_group;" ::: "memory")
#define CP_WAIT0()  asm volatile("cp.async.wait_group 0;" ::: "memory")

// fp16 MMA, fp32 accumulate
__device__ __forceinline__ void mma16(float* d, const uint32_t* a, const uint32_t* b) {
    asm volatile(
        "mma.sync.aligned.m16n8k16.row.col.f32.f16.f16.f32 "
        "{%0,%1,%2,%3}, {%4,%5,%6,%7}, {%8,%9}, {%0,%1,%2,%3};\n"
        : "+f"(d[0]), "+f"(d[1]), "+f"(d[2]), "+f"(d[3])
        : "r"(a[0]), "r"(a[1]), "r"(a[2]), "r"(a[3]),
          "r"(b[0]), "r"(b[1]));
}

__device__ __forceinline__ void ldsm4(uint32_t* r, uint32_t addr) {
    asm volatile("ldmatrix.sync.aligned.m8n8.x4.shared.b16 {%0,%1,%2,%3}, [%4];"
                 : "=r"(r[0]), "=r"(r[1]), "=r"(r[2]), "=r"(r[3]) : "r"(addr));
}

__device__ __forceinline__ uint32_t h2u(__half2 h) {
    return *(const uint32_t*)&h;
}

#define STAGE_BYTES 32768      // A 16KB + B 16KB (128 rows x 128B, k-slab = 64 halves)
#define GEMM_SMEM (2 * STAGE_BYTES)   // 64 KB -> 2 CTAs/SM

// ---------------- 0. reset ----------------
__global__ void reset_kernel() {
    if (threadIdx.x < NE) g_cursor[threadIdx.x] = 0;
    if (threadIdx.x == 0) g_wq = 0;
}

// ---------------- 1. prep: w13 -> fp16 | gate + scatter + x -> fp16 ----------------
#define PREP_W13 2048
#define PREP_GATE (NTOK / 8)   // 1024

__global__ __launch_bounds__(256) void prep_kernel(const float* __restrict__ w13,
                                                   const float* __restrict__ x,
                                                   const float* __restrict__ gw) {
    int b = blockIdx.x;
    if (b < PREP_W13) {
        const size_t ng = (size_t)NE * 2 * INTER * HID / 8;
        for (size_t g = (size_t)b * blockDim.x + threadIdx.x; g < ng;
             g += (size_t)PREP_W13 * blockDim.x) {
            const float4* src = (const float4*)(w13 + g * 8);
            float4 lo = src[0], hi = src[1];
            uint4 o;
            o.x = h2u(__floats2half2_rn(lo.x, lo.y));
            o.y = h2u(__floats2half2_rn(lo.z, lo.w));
            o.z = h2u(__floats2half2_rn(hi.x, hi.y));
            o.w = h2u(__floats2half2_rn(hi.z, hi.w));
            ((uint4*)c_w13)[g] = o;
        }
    } else {
        // gate + scatter + x->fp16
        int gb = b - PREP_W13;
        int warp = threadIdx.x >> 5;
        int lane = threadIdx.x & 31;
        int t = gb * 8 + warp;
        if (t >= NTOK) return;

        const float4* xp = (const float4*)(x + (size_t)t * HID);
        uint2* cxp = (uint2*)(c_x + (size_t)t * HID);
        float acc[NE];
#pragma unroll
        for (int e = 0; e < NE; e++) acc[e] = 0.f;

        for (int kk = 0; kk < HID / 4; kk += 32) {
            float4 xv = xp[kk + lane];
            uint2 hx;
            hx.x = h2u(__floats2half2_rn(xv.x, xv.y));
            hx.y = h2u(__floats2half2_rn(xv.z, xv.w));
            cxp[kk + lane] = hx;
#pragma unroll
            for (int e = 0; e < NE; e++) {
                float4 g = ((const float4*)(gw + (size_t)e * HID))[kk + lane];
                acc[e] += xv.x * g.x + xv.y * g.y + xv.z * g.z + xv.w * g.w;
            }
        }
#pragma unroll
        for (int e = 0; e < NE; e++) {
#pragma unroll
            for (int o = 16; o > 0; o >>= 1)
                acc[e] += __shfl_xor_sync(0xffffffffu, acc[e], o);
        }
        if (lane == 0) {
            float mx = acc[0];
#pragma unroll
            for (int e = 1; e < NE; e++) mx = fmaxf(mx, acc[e]);
            float p[NE], s = 0.f;
#pragma unroll
            for (int e = 0; e < NE; e++) { p[e] = __expf(acc[e] - mx); s += p[e]; }
            float inv = 1.f / s;
            int i0 = 0; float v0 = p[0];
#pragma unroll
            for (int e = 1; e < NE; e++) if (p[e] > v0) { v0 = p[e]; i0 = e; }
            int i1 = -1; float v1 = -1.f;
#pragma unroll
            for (int e = 0; e < NE; e++) if (e != i0 && p[e] > v1) { v1 = p[e]; i1 = e; }
            int pos0 = atomicAdd(&g_cursor[i0], 1);
            g_list_c[i0 * CAP + pos0] = t * 2;
            g_list_w[i0 * CAP + pos0] = v0 * inv;
            int pos1 = atomicAdd(&g_cursor[i1], 1);
            g_list_c[i1 * CAP + pos1] = t * 2 + 1;
            g_list_w[i1 * CAP + pos1] = v1 * inv;
        }
    }
}

// ---------------- shared GEMM macros ----------------
#define G_PREFETCH(SB, K0) do {                                          \
    _Pragma("unroll")                                                    \
    for (int i = 0; i < 4; i++) {                                        \
        cpasync16((SB) + dsto[i], asrc[i] + (K0), assz[i]);              \
        cpasync16((SB) + 16384 + dsto[i], bsrc[i] + (K0), 16);           \
    }                                                                    \
    CP_COMMIT();                                                         \
} while (0)

// idle-CTA side work: grabs 0..ZGRABS-1 zero `out`; grabs ZGRABS.. convert w2.
#define ZGRABS 2048                         // NTOK*HID/4 float4 / 2048 per grab
#define WGRABS 2816                         // NE*HID*INTER/8 groups / 2048 per grab
#define TOTAL_GRABS (ZGRABS + WGRABS)

// ---------------- 2. GEMM1: h = silu(X Wg^T) * (X Wu^T) ----------------
// Idle CTAs (rt beyond this expert's rows) drain the w2-convert / out-zero work queue.
#define NS1 (HID / 64)   // 32 (even)

#define G1_COMPUTE(STG) do {                                             \
    uint32_t stA_ = sbase + (STG) * STAGE_BYTES;                         \
    uint32_t stB_ = stA_ + 16384;                                        \
    _Pragma("unroll")                                                    \
    for (int ks = 0; ks < 4; ks++) {                                     \
        uint32_t aoff = ((uint32_t)(ks * 32) + aKoff) ^ xorv;            \
        uint32_t boff = ((uint32_t)(ks * 32) + bKoff) ^ xorv;            \
        uint32_t af[2][4], qg[2][4], qu[2][4];                           \
        _Pragma("unroll")                                                \
        for (int mt = 0; mt < 2; mt++)                                   \
            ldsm4(af[mt], stA_ + aRowB + (uint32_t)(mt * 2048) + aoff);  \
        _Pragma("unroll")                                                \
        for (int p = 0; p < 2; p++) {                                    \
            ldsm4(qg[p], stB_ + bgRow[p] + boff);                        \
            ldsm4(qu[p], stB_ + buRow[p] + boff);                        \
        }                                                                \
        _Pragma("unroll")                                                \
        for (int nt = 0; nt < 4; nt++) {                                 \
            int p = nt >> 1, h = (nt & 1) * 2;                           \
            uint32_t bg[2] = { qg[p][h], qg[p][h + 1] };                 \
            uint32_t bu[2] = { qu[p][h], qu[p][h + 1] };                 \
            _Pragma("unroll")                                            \
            for (int mt = 0; mt < 2; mt++) {                             \
                mma16(cg[mt][nt], af[mt], bg);                           \
                mma16(cu[mt][nt], af[mt], bu);                           \
            }                                                            \
        }                                                                \
    }                                                                    \
} while (0)

__global__ __launch_bounds__(256, 2) void gemm1_kernel(const float* __restrict__ w2,
                                                       float* __restrict__ out) {
    __shared__ unsigned int sh_grab;
    int e = blockIdx.z;
    int cnt = g_cursor[e];
    int rt = blockIdx.y;
    int tid = threadIdx.x;

    if (rt * 128 >= cnt) {
        // idle CTA: drain side-work queue (zero out / convert w2)
        for (;;) {
            if (tid == 0) sh_grab = atomicAdd(&g_wq, 1u);
            __syncthreads();
            unsigned int g = sh_grab;
            __syncthreads();
            if (g >= TOTAL_GRABS) return;
            if (g < ZGRABS) {
                float4* dst = (float4*)out + (size_t)g * 2048;
#pragma unroll
                for (int i = 0; i < 8; i++)
                    dst[i * 256 + tid] = make_float4(0.f, 0.f, 0.f, 0.f);
            } else {
                size_t base = (size_t)(g - ZGRABS) * 2048;
#pragma unroll
                for (int i = 0; i < 8; i++) {
                    size_t idx = base + i * 256 + tid;
                    const float4* src = (const float4*)(w2 + idx * 8);
                    float4 lo = src[0], hi = src[1];
                    uint4 o;
                    o.x = h2u(__floats2half2_rn(lo.x, lo.y));
                    o.y = h2u(__floats2half2_rn(lo.z, lo.w));
                    o.z = h2u(__floats2half2_rn(hi.x, hi.y));
                    o.w = h2u(__floats2half2_rn(hi.z, hi.w));
                    ((uint4*)c_w2)[idx] = o;
                }
            }
        }
    }

    int ct = blockIdx.x;
    extern __shared__ char sm[];
    uint32_t sbase = smem_u32(sm);

    int lane = tid & 31, wid = tid >> 5;
    int wm = wid >> 1, wn = wid & 1;

    const __half* asrc[4];
    const __half* bsrc[4];
    int assz[4];
    uint32_t dsto[4];
#pragma unroll
    for (int i = 0; i < 4; i++) {
        int idx = i * 256 + tid;
        int r = idx >> 3;
        int q = idx & 7;
        int ridx = rt * 128 + r;
        int tok = (ridx < cnt) ? (g_list_c[e * CAP + ridx] >> 1) : 0;
        asrc[i] = c_x + (size_t)tok * HID + q * 8;
        assz[i] = (ridx < cnt) ? 16 : 0;
        int grow = (r < 64) ? (ct * 64 + r) : (INTER + ct * 64 + (r - 64));
        bsrc[i] = c_w13 + ((size_t)e * 2 * INTER + grow) * HID + q * 8;
        dsto[i] = (uint32_t)(r * 128 + ((q * 16) ^ ((r & 7) << 4)));
    }

    int mi = lane >> 3, l7 = lane & 7;
    uint32_t xorv = (uint32_t)(l7 << 4);
    uint32_t aKoff = (uint32_t)((mi >> 1) << 4);
    uint32_t bKoff = (uint32_t)((mi & 1) << 4);
    uint32_t aRowB = (uint32_t)((wm * 32 + ((mi & 1) << 3) + l7) * 128);
    int bRowSel = ((mi >> 1) << 3) + l7;
    uint32_t bgRow[2], buRow[2];
#pragma unroll
    for (int p = 0; p < 2; p++) {
        bgRow[p] = (uint32_t)((wn * 32 + p * 16 + bRowSel) * 128);
        buRow[p] = (uint32_t)((64 + wn * 32 + p * 16 + bRowSel) * 128);
    }

    float cg[2][4][4], cu[2][4][4];
#pragma unroll
    for (int mt = 0; mt < 2; mt++)
#pragma unroll
        for (int nt = 0; nt < 4; nt++)
#pragma unroll
            for (int q = 0; q < 4; q++) { cg[mt][nt][q] = 0.f; cu[mt][nt][q] = 0.f; }

    G_PREFETCH(sbase, 0);

    int k0 = 64;
    for (int s2 = 0; s2 < NS1 / 2; s2++) {
        CP_WAIT0();
        __syncthreads();
        G_PREFETCH(sbase + STAGE_BYTES, k0);
        k0 += 64;
        G1_COMPUTE(0);
        CP_WAIT0();
        __syncthreads();
        if (k0 < HID) {
            G_PREFETCH(sbase, k0);
            k0 += 64;
        }
        G1_COMPUTE(1);
    }

    // epilogue: h = silu(g) * u, stored fp16
#pragma unroll
    for (int mt = 0; mt < 2; mt++) {
        int rb = wm * 32 + mt * 16 + (lane >> 2);
#pragma unroll
        for (int half = 0; half < 2; half++) {
            int ridx = rt * 128 + rb + half * 8;
            if (ridx < cnt) {
                __half* hp = g_h + ((size_t)e * CAP + ridx) * INTER + (size_t)ct * 64;
#pragma unroll
                for (int nt = 0; nt < 4; nt++) {
                    int cc = wn * 32 + nt * 8 + (lane & 3) * 2;
                    float gv0 = cg[mt][nt][half * 2 + 0], gv1 = cg[mt][nt][half * 2 + 1];
                    float uv0 = cu[mt][nt][half * 2 + 0], uv1 = cu[mt][nt][half * 2 + 1];
                    float h0 = gv0 * (1.f / (1.f + __expf(-gv0))) * uv0;
                    float h1 = gv1 * (1.f / (1.f + __expf(-gv1))) * uv1;
                    *(__half2*)(hp + cc) = __floats2half2_rn(h0, h1);
                }
            }
        }
    }
}

// ---------------- 3. GEMM2: out[t] += w_c * (h W2^T) ----------------
#define NS2 (INTER / 64)  // 44 (even)

#define G2_COMPUTE(STG) do {                                             \
    uint32_t stA_ = sbase + (STG) * STAGE_BYTES;                         \
    uint32_t stB_ = stA_ + 16384;                                        \
    _Pragma("unroll")                                                    \
    for (int ks = 0; ks < 4; ks++) {                                     \
        uint32_t aoff = ((uint32_t)(ks * 32) + aKoff) ^ xorv;            \
        uint32_t boff = ((uint32_t)(ks * 32) + bKoff) ^ xorv;            \
        uint32_t af[2][4], qb[4][4];                                     \
        _Pragma("unroll")                                                \
        for (int mt = 0; mt < 2; mt++)                                   \
            ldsm4(af[mt], stA_ + aRowB + (uint32_t)(mt * 2048) + aoff);  \
        _Pragma("unroll")                                                \
        for (int p = 0; p < 4; p++)                                      \
            ldsm4(qb[p], stB_ + bRow[p] + boff);                         \
        _Pragma("unroll")                                                \
        for (int nt = 0; nt < 8; nt++) {                                 \
            int p = nt >> 1, h = (nt & 1) * 2;                           \
            uint32_t bf[2] = { qb[p][h], qb[p][h + 1] };                 \
            _Pragma("unroll")                                            \
            for (int mt = 0; mt < 2; mt++)                               \
                mma16(acc[mt][nt], af[mt], bf);                          \
        }                                                                \
    }                                                                    \
} while (0)

__global__ __launch_bounds__(256, 2) void gemm2_kernel(float* __restrict__ out) {
    int e = blockIdx.z;
    int cnt = g_cursor[e];
    int rt = blockIdx.y;
    if (rt * 128 >= cnt) return;
    int ctn = blockIdx.x;

    extern __shared__ char sm[];
    uint32_t sbase = smem_u32(sm);

    int tid = threadIdx.x;
    int lane = tid & 31, wid = tid >> 5;
    int wm = wid >> 1, wn = wid & 1;

    const __half* asrc[4];
    const __half* bsrc[4];
    int assz[4];
    uint32_t dsto[4];
#pragma unroll
    for (int i = 0; i < 4; i++) {
        int idx = i * 256 + tid;
        int r = idx >> 3;
        int q = idx & 7;
        int ridx = rt * 128 + r;
        asrc[i] = g_h + ((size_t)e * CAP + ridx) * INTER + q * 8;
        assz[i] = (ridx < cnt) ? 16 : 0;
        bsrc[i] = c_w2 + ((size_t)e * HID + ctn * 128 + r) * INTER + q * 8;
        dsto[i] = (uint32_t)(r * 128 + ((q * 16) ^ ((r & 7) << 4)));
    }

    int mi = lane >> 3, l7 = lane & 7;
    uint32_t xorv = (uint32_t)(l7 << 4);
    uint32_t aKoff = (uint32_t)((mi >> 1) << 4);
    uint32_t bKoff = (uint32_t)((mi & 1) << 4);
    uint32_t aRowB = (uint32_t)((wm * 32 + ((mi & 1) << 3) + l7) * 128);
    int bRowSel = ((mi >> 1) << 3) + l7;
    uint32_t bRow[4];
#pragma unroll
    for (int p = 0; p < 4; p++)
        bRow[p] = (uint32_t)((wn * 64 + p * 16 + bRowSel) * 128);

    float acc[2][8][4];
#pragma unroll
    for (int mt = 0; mt < 2; mt++)
#pragma unroll
        for (int nt = 0; nt < 8; nt++)
#pragma unroll
            for (int q = 0; q < 4; q++) acc[mt][nt][q] = 0.f;

    G_PREFETCH(sbase, 0);

    int k0 = 64;
    for (int s2 = 0; s2 < NS2 / 2; s2++) {
        CP_WAIT0();
        __syncthreads();
        G_PREFETCH(sbase + STAGE_BYTES, k0);
        k0 += 64;
        G2_COMPUTE(0);
        CP_WAIT0();
        __syncthreads();
        if (k0 < INTER) {
            G_PREFETCH(sbase, k0);
            k0 += 64;
        }
        G2_COMPUTE(1);
    }

    // epilogue: atomic-accumulate weighted result directly into out
#pragma unroll
    for (int mt = 0; mt < 2; mt++) {
        int rb = wm * 32 + mt * 16 + (lane >> 2);
#pragma unroll
        for (int half = 0; half < 2; half++) {
            int ridx = rt * 128 + rb + half * 8;
            if (ridx < cnt) {
                float w = g_list_w[e * CAP + ridx];
                int   t = g_list_c[e * CAP + ridx] >> 1;
                float* yp = out + (size_t)t * HID + (size_t)ctn * 128;
#pragma unroll
                for (int nt = 0; nt < 8; nt++) {
                    int cc = wn * 64 + nt * 8 + (lane & 3) * 2;
                    atomicAdd(yp + cc,     w * acc[mt][nt][half * 2 + 0]);
                    atomicAdd(yp + cc + 1, w * acc[mt][nt][half * 2 + 1]);
                }
            }
        }
    }
}

// ---------------- launch ----------------
extern "C" void kernel_launch(void* const* d_in, const int* in_sizes, int n_in,
                              void* d_out, int out_size) {
    const float* x   = (const float*)d_in[0];
    const float* gw  = (const float*)d_in[1];
    const float* w13 = (const float*)d_in[2];
    const float* w2  = (const float*)d_in[3];
    float* out = (float*)d_out;

    cudaFuncSetAttribute(gemm1_kernel, cudaFuncAttributeMaxDynamicSharedMemorySize, GEMM_SMEM);
    cudaFuncSetAttribute(gemm2_kernel, cudaFuncAttributeMaxDynamicSharedMemorySize, GEMM_SMEM);

    reset_kernel<<<1, 32>>>();                                             // launch 0
    prep_kernel<<<PREP_W13 + PREP_GATE, 256>>>(w13, x, gw);                // launch 1
    gemm1_kernel<<<dim3(INTER / 64, CAP / 128, NE), 256, GEMM_SMEM>>>(w2, out); // launch 2
    gemm2_kernel<<<dim3(HID / 128, CAP / 128, NE), 256, GEMM_SMEM>>>(out); // launch 3 (ncu)
}

// round 13
// speedup vs baseline: 1.1490x; 1.1490x over previous
#include <cuda_runtime.h>
#include <cuda_fp16.h>
#include <cstdint>
#include <cstddef>

#define NE    8
#define HID   2048
#define INTER 2816
#define NTOK  8192
#define CAP   8192             // cnt_e <= NTOK: a token routes to an expert at most once

// ---------------- scratch (device globals; no runtime allocation) ----------------
__device__ int    g_cursor[NE];
__device__ int    g_list_c[NE * CAP];          // token*2 + slot
__device__ float  g_list_w[NE * CAP];
__device__ __half c_x[(size_t)NTOK * HID];             // fp16 x   (33 MB)
__device__ __half c_w13[(size_t)NE * 2 * INTER * HID]; // fp16 w13 (184 MB)
__device__ __half c_w2[(size_t)NE * HID * INTER];      // fp16 w2  (92 MB)
__device__ __half g_h[(size_t)NE * CAP * INTER];       // fp16 h   (369 MB)

// ---------------- helpers ----------------
__device__ __forceinline__ uint32_t smem_u32(const void* p) {
    uint32_t a;
    asm("{ .reg .u64 t; cvta.to.shared.u64 t, %1; cvt.u32.u64 %0, t; }" : "=r"(a) : "l"(p));
    return a;
}
__device__ __forceinline__ void cpasync16(uint32_t dst, const void* src, int srcsize) {
    asm volatile("cp.async.cg.shared.global [%0], [%1], 16, %2;"
                 :: "r"(dst), "l"(src), "r"(srcsize) : "memory");
}
#define CP_COMMIT() asm volatile("cp.async.commit_group;" ::: "memory")
#define CP_WAIT0()  asm volatile("cp.async.wait_group 0;" ::: "memory")

// fp16 MMA, fp32 accumulate: D(16x8) += A(16x16) * B(8x16)^T
__device__ __forceinline__ void mma16(float* d, const uint32_t* a, const uint32_t* b) {
    asm volatile(
        "mma.sync.aligned.m16n8k16.row.col.f32.f16.f16.f32 "
        "{%0,%1,%2,%3}, {%4,%5,%6,%7}, {%8,%9}, {%0,%1,%2,%3};\n"
        : "+f"(d[0]), "+f"(d[1]), "+f"(d[2]), "+f"(d[3])
        : "r"(a[0]), "r"(a[1]), "r"(a[2]), "r"(a[3]),
          "r"(b[0]), "r"(b[1]));
}

// ldmatrix: 4x (8x8 b16) matrices, one instruction, per-lane row addresses
__device__ __forceinline__ void ldsm4(uint32_t* r, uint32_t addr) {
    asm volatile("ldmatrix.sync.aligned.m8n8.x4.shared.b16 {%0,%1,%2,%3}, [%4];"
                 : "=r"(r[0]), "=r"(r[1]), "=r"(r[2]), "=r"(r[3]) : "r"(addr));
}

__device__ __forceinline__ uint32_t h2u(__half2 h) {
    return *(const uint32_t*)&h;
}

#define STAGE_BYTES 32768      // A 16KB + B 16KB (128 rows x 128B, k-slab = 64 halves)
#define GEMM_SMEM (2 * STAGE_BYTES)   // 64 KB -> 2 CTAs/SM

// ---------------- 0. reset cursors ----------------
__global__ void reset_kernel() {
    if (threadIdx.x < NE) g_cursor[threadIdx.x] = 0;
}

// ---------------- 1. fused prep: w13 conv | w2 conv + zero out | gate(+c_x) ----------------
#define PREP_W13 2048
#define PREP_W2  2048
#define PREP_GATE (NTOK / 8)   // 1024

__global__ __launch_bounds__(256) void prep_kernel(const float* __restrict__ w13,
                                                   const float* __restrict__ w2,
                                                   const float* __restrict__ x,
                                                   const float* __restrict__ gw,
                                                   float* __restrict__ out) {
    int b = blockIdx.x;
    if (b < PREP_W13) {
        const size_t ng = (size_t)NE * 2 * INTER * HID / 8;
        for (size_t g = (size_t)b * blockDim.x + threadIdx.x; g < ng;
             g += (size_t)PREP_W13 * blockDim.x) {
            const float4* src = (const float4*)(w13 + g * 8);
            float4 lo = src[0], hi = src[1];
            uint4 o;
            o.x = h2u(__floats2half2_rn(lo.x, lo.y));
            o.y = h2u(__floats2half2_rn(lo.z, lo.w));
            o.z = h2u(__floats2half2_rn(hi.x, hi.y));
            o.w = h2u(__floats2half2_rn(hi.z, hi.w));
            ((uint4*)c_w13)[g] = o;
        }
    } else if (b < PREP_W13 + PREP_W2) {
        int bb = b - PREP_W13;
        const size_t nz = (size_t)NTOK * HID / 4;
        for (size_t i = (size_t)bb * blockDim.x + threadIdx.x; i < nz;
             i += (size_t)PREP_W2 * blockDim.x)
            ((float4*)out)[i] = make_float4(0.f, 0.f, 0.f, 0.f);
        const size_t nw = (size_t)NE * HID * INTER / 8;
        for (size_t g = (size_t)bb * blockDim.x + threadIdx.x; g < nw;
             g += (size_t)PREP_W2 * blockDim.x) {
            const float4* src = (const float4*)(w2 + g * 8);
            float4 lo = src[0], hi = src[1];
            uint4 o;
            o.x = h2u(__floats2half2_rn(lo.x, lo.y));
            o.y = h2u(__floats2half2_rn(lo.z, lo.w));
            o.z = h2u(__floats2half2_rn(hi.x, hi.y));
            o.w = h2u(__floats2half2_rn(hi.z, hi.w));
            ((uint4*)c_w2)[g] = o;
        }
    } else {
        // gate + scatter + x->fp16
        int gb = b - PREP_W13 - PREP_W2;
        int warp = threadIdx.x >> 5;
        int lane = threadIdx.x & 31;
        int t = gb * 8 + warp;
        if (t >= NTOK) return;

        const float4* xp = (const float4*)(x + (size_t)t * HID);
        uint2* cxp = (uint2*)(c_x + (size_t)t * HID);
        float acc[NE];
#pragma unroll
        for (int e = 0; e < NE; e++) acc[e] = 0.f;

        for (int kk = 0; kk < HID / 4; kk += 32) {
            float4 xv = xp[kk + lane];
            uint2 hx;
            hx.x = h2u(__floats2half2_rn(xv.x, xv.y));
            hx.y = h2u(__floats2half2_rn(xv.z, xv.w));
            cxp[kk + lane] = hx;
#pragma unroll
            for (int e = 0; e < NE; e++) {
                float4 g = ((const float4*)(gw + (size_t)e * HID))[kk + lane];
                acc[e] += xv.x * g.x + xv.y * g.y + xv.z * g.z + xv.w * g.w;
            }
        }
#pragma unroll
        for (int e = 0; e < NE; e++) {
#pragma unroll
            for (int o = 16; o > 0; o >>= 1)
                acc[e] += __shfl_xor_sync(0xffffffffu, acc[e], o);
        }
        if (lane == 0) {
            float mx = acc[0];
#pragma unroll
            for (int e = 1; e < NE; e++) mx = fmaxf(mx, acc[e]);
            float p[NE], s = 0.f;
#pragma unroll
            for (int e = 0; e < NE; e++) { p[e] = __expf(acc[e] - mx); s += p[e]; }
            float inv = 1.f / s;
            int i0 = 0; float v0 = p[0];
#pragma unroll
            for (int e = 1; e < NE; e++) if (p[e] > v0) { v0 = p[e]; i0 = e; }
            int i1 = -1; float v1 = -1.f;
#pragma unroll
            for (int e = 0; e < NE; e++) if (e != i0 && p[e] > v1) { v1 = p[e]; i1 = e; }
            int pos0 = atomicAdd(&g_cursor[i0], 1);
            g_list_c[i0 * CAP + pos0] = t * 2;
            g_list_w[i0 * CAP + pos0] = v0 * inv;
            int pos1 = atomicAdd(&g_cursor[i1], 1);
            g_list_c[i1 * CAP + pos1] = t * 2 + 1;
            g_list_w[i1 * CAP + pos1] = v1 * inv;
        }
    }
}

// ---------------- shared GEMM macros ----------------
#define G_PREFETCH(SB, K0) do {                                          \
    _Pragma("unroll")                                                    \
    for (int i = 0; i < 4; i++) {                                        \
        cpasync16((SB) + dsto[i], asrc[i] + (K0), assz[i]);              \
        cpasync16((SB) + 16384 + dsto[i], bsrc[i] + (K0), 16);           \
    }                                                                    \
    CP_COMMIT();                                                         \
} while (0)

// ---------------- 2. GEMM1: h = silu(X Wg^T) * (X Wu^T) ----------------
// 2-stage cp.async, 1 barrier/slab, unrolled x2 with literal stage ids.
#define NS1 (HID / 64)   // 32 (even)

#define G1_COMPUTE(STG) do {                                             \
    uint32_t stA_ = sbase + (STG) * STAGE_BYTES;                         \
    uint32_t stB_ = stA_ + 16384;                                        \
    _Pragma("unroll")                                                    \
    for (int ks = 0; ks < 4; ks++) {                                     \
        uint32_t aoff = ((uint32_t)(ks * 32) + aKoff) ^ xorv;            \
        uint32_t boff = ((uint32_t)(ks * 32) + bKoff) ^ xorv;            \
        uint32_t af[2][4], qg[2][4], qu[2][4];                           \
        _Pragma("unroll")                                                \
        for (int mt = 0; mt < 2; mt++)                                   \
            ldsm4(af[mt], stA_ + aRowB + (uint32_t)(mt * 2048) + aoff);  \
        _Pragma("unroll")                                                \
        for (int p = 0; p < 2; p++) {                                    \
            ldsm4(qg[p], stB_ + bgRow[p] + boff);                        \
            ldsm4(qu[p], stB_ + buRow[p] + boff);                        \
        }                                                                \
        _Pragma("unroll")                                                \
        for (int nt = 0; nt < 4; nt++) {                                 \
            int p = nt >> 1, h = (nt & 1) * 2;                           \
            uint32_t bg[2] = { qg[p][h], qg[p][h + 1] };                 \
            uint32_t bu[2] = { qu[p][h], qu[p][h + 1] };                 \
            _Pragma("unroll")                                            \
            for (int mt = 0; mt < 2; mt++) {                             \
                mma16(cg[mt][nt], af[mt], bg);                           \
                mma16(cu[mt][nt], af[mt], bu);                           \
            }                                                            \
        }                                                                \
    }                                                                    \
} while (0)

__global__ __launch_bounds__(256, 2) void gemm1_kernel() {
    int e = blockIdx.z;
    int cnt = g_cursor[e];
    int rt = blockIdx.y;
    if (rt * 128 >= cnt) return;
    int ct = blockIdx.x;

    extern __shared__ char sm[];
    uint32_t sbase = smem_u32(sm);

    int tid = threadIdx.x;
    int lane = tid & 31, wid = tid >> 5;
    int wm = wid >> 1, wn = wid & 1;

    const __half* asrc[4];
    const __half* bsrc[4];
    int assz[4];
    uint32_t dsto[4];
#pragma unroll
    for (int i = 0; i < 4; i++) {
        int idx = i * 256 + tid;
        int r = idx >> 3;            // 0..127
        int q = idx & 7;             // 16B chunk in 128B row
        int ridx = rt * 128 + r;
        int tok = (ridx < cnt) ? (g_list_c[e * CAP + ridx] >> 1) : 0;
        asrc[i] = c_x + (size_t)tok * HID + q * 8;
        assz[i] = (ridx < cnt) ? 16 : 0;
        int grow = (r < 64) ? (ct * 64 + r) : (INTER + ct * 64 + (r - 64));
        bsrc[i] = c_w13 + ((size_t)e * 2 * INTER + grow) * HID + q * 8;
        dsto[i] = (uint32_t)(r * 128 + ((q * 16) ^ ((r & 7) << 4)));
    }

    // ldmatrix per-lane addressing
    int mi = lane >> 3, l7 = lane & 7;
    uint32_t xorv = (uint32_t)(l7 << 4);
    uint32_t aKoff = (uint32_t)((mi >> 1) << 4);
    uint32_t bKoff = (uint32_t)((mi & 1) << 4);
    uint32_t aRowB = (uint32_t)((wm * 32 + ((mi & 1) << 3) + l7) * 128);
    int bRowSel = ((mi >> 1) << 3) + l7;
    uint32_t bgRow[2], buRow[2];
#pragma unroll
    for (int p = 0; p < 2; p++) {
        bgRow[p] = (uint32_t)((wn * 32 + p * 16 + bRowSel) * 128);
        buRow[p] = (uint32_t)((64 + wn * 32 + p * 16 + bRowSel) * 128);
    }

    float cg[2][4][4], cu[2][4][4];
#pragma unroll
    for (int mt = 0; mt < 2; mt++)
#pragma unroll
        for (int nt = 0; nt < 4; nt++)
#pragma unroll
            for (int q = 0; q < 4; q++) { cg[mt][nt][q] = 0.f; cu[mt][nt][q] = 0.f; }

    // prologue: slab 0 -> stage 0
    G_PREFETCH(sbase, 0);

    int k0 = 64;
    for (int s2 = 0; s2 < NS1 / 2; s2++) {
        CP_WAIT0();
        __syncthreads();
        G_PREFETCH(sbase + STAGE_BYTES, k0);
        k0 += 64;
        G1_COMPUTE(0);
        CP_WAIT0();
        __syncthreads();
        if (k0 < HID) {
            G_PREFETCH(sbase, k0);
            k0 += 64;
        }
        G1_COMPUTE(1);
    }

    // epilogue: h = silu(g) * u, stored fp16
#pragma unroll
    for (int mt = 0; mt < 2; mt++) {
        int rb = wm * 32 + mt * 16 + (lane >> 2);
#pragma unroll
        for (int half = 0; half < 2; half++) {
            int ridx = rt * 128 + rb + half * 8;
            if (ridx < cnt) {
                __half* hp = g_h + ((size_t)e * CAP + ridx) * INTER + (size_t)ct * 64;
#pragma unroll
                for (int nt = 0; nt < 4; nt++) {
                    int cc = wn * 32 + nt * 8 + (lane & 3) * 2;
                    float gv0 = cg[mt][nt][half * 2 + 0], gv1 = cg[mt][nt][half * 2 + 1];
                    float uv0 = cu[mt][nt][half * 2 + 0], uv1 = cu[mt][nt][half * 2 + 1];
                    float h0 = gv0 * (1.f / (1.f + __expf(-gv0))) * uv0;
                    float h1 = gv1 * (1.f / (1.f + __expf(-gv1))) * uv1;
                    *(__half2*)(hp + cc) = __floats2half2_rn(h0, h1);
                }
            }
        }
    }
}

// ---------------- 3. GEMM2: out[t] += w_c * (h W2^T) ----------------
#define NS2 (INTER / 64)  // 44 (even)

#define G2_COMPUTE(STG) do {                                             \
    uint32_t stA_ = sbase + (STG) * STAGE_BYTES;                         \
    uint32_t stB_ = stA_ + 16384;                                        \
    _Pragma("unroll")                                                    \
    for (int ks = 0; ks < 4; ks++) {                                     \
        uint32_t aoff = ((uint32_t)(ks * 32) + aKoff) ^ xorv;            \
        uint32_t boff = ((uint32_t)(ks * 32) + bKoff) ^ xorv;            \
        uint32_t af[2][4], qb[4][4];                                     \
        _Pragma("unroll")                                                \
        for (int mt = 0; mt < 2; mt++)                                   \
            ldsm4(af[mt], stA_ + aRowB + (uint32_t)(mt * 2048) + aoff);  \
        _Pragma("unroll")                                                \
        for (int p = 0; p < 4; p++)                                      \
            ldsm4(qb[p], stB_ + bRow[p] + boff);                         \
        _Pragma("unroll")                                                \
        for (int nt = 0; nt < 8; nt++) {                                 \
            int p = nt >> 1, h = (nt & 1) * 2;                           \
            uint32_t bf[2] = { qb[p][h], qb[p][h + 1] };                 \
            _Pragma("unroll")                                            \
            for (int mt = 0; mt < 2; mt++)                               \
                mma16(acc[mt][nt], af[mt], bf);                          \
        }                                                                \
    }                                                                    \
} while (0)

__global__ __launch_bounds__(256, 2) void gemm2_kernel(float* __restrict__ out) {
    int e = blockIdx.z;
    int cnt = g_cursor[e];
    int rt = blockIdx.y;
    if (rt * 128 >= cnt) return;
    int ctn = blockIdx.x;

    extern __shared__ char sm[];
    uint32_t sbase = smem_u32(sm);

    int tid = threadIdx.x;
    int lane = tid & 31, wid = tid >> 5;
    int wm = wid >> 1, wn = wid & 1;

    const __half* asrc[4];
    const __half* bsrc[4];
    int assz[4];
    uint32_t dsto[4];
#pragma unroll
    for (int i = 0; i < 4; i++) {
        int idx = i * 256 + tid;
        int r = idx >> 3;
        int q = idx & 7;
        int ridx = rt * 128 + r;
        asrc[i] = g_h + ((size_t)e * CAP + ridx) * INTER + q * 8;
        assz[i] = (ridx < cnt) ? 16 : 0;
        bsrc[i] = c_w2 + ((size_t)e * HID + ctn * 128 + r) * INTER + q * 8;
        dsto[i] = (uint32_t)(r * 128 + ((q * 16) ^ ((r & 7) << 4)));
    }

    // ldmatrix per-lane addressing
    int mi = lane >> 3, l7 = lane & 7;
    uint32_t xorv = (uint32_t)(l7 << 4);
    uint32_t aKoff = (uint32_t)((mi >> 1) << 4);
    uint32_t bKoff = (uint32_t)((mi & 1) << 4);
    uint32_t aRowB = (uint32_t)((wm * 32 + ((mi & 1) << 3) + l7) * 128);
    int bRowSel = ((mi >> 1) << 3) + l7;
    uint32_t bRow[4];
#pragma unroll
    for (int p = 0; p < 4; p++)
        bRow[p] = (uint32_t)((wn * 64 + p * 16 + bRowSel) * 128);

    float acc[2][8][4];
#pragma unroll
    for (int mt = 0; mt < 2; mt++)
#pragma unroll
        for (int nt = 0; nt < 8; nt++)
#pragma unroll
            for (int q = 0; q < 4; q++) acc[mt][nt][q] = 0.f;

    // prologue: slab 0 -> stage 0
    G_PREFETCH(sbase, 0);

    int k0 = 64;
    for (int s2 = 0; s2 < NS2 / 2; s2++) {
        CP_WAIT0();
        __syncthreads();
        G_PREFETCH(sbase + STAGE_BYTES, k0);
        k0 += 64;
        G2_COMPUTE(0);
        CP_WAIT0();
        __syncthreads();
        if (k0 < INTER) {
            G_PREFETCH(sbase, k0);
            k0 += 64;
        }
        G2_COMPUTE(1);
    }

    // epilogue: atomic-accumulate weighted result directly into out
#pragma unroll
    for (int mt = 0; mt < 2; mt++) {
        int rb = wm * 32 + mt * 16 + (lane >> 2);
#pragma unroll
        for (int half = 0; half < 2; half++) {
            int ridx = rt * 128 + rb + half * 8;
            if (ridx < cnt) {
                float w = g_list_w[e * CAP + ridx];
                int   t = g_list_c[e * CAP + ridx] >> 1;
                float* yp = out + (size_t)t * HID + (size_t)ctn * 128;
#pragma unroll
                for (int nt = 0; nt < 8; nt++) {
                    int cc = wn * 64 + nt * 8 + (lane & 3) * 2;
                    atomicAdd(yp + cc,     w * acc[mt][nt][half * 2 + 0]);
                    atomicAdd(yp + cc + 1, w * acc[mt][nt][half * 2 + 1]);
                }
            }
        }
    }
}

// ---------------- launch ----------------
extern "C" void kernel_launch(void* const* d_in, const int* in_sizes, int n_in,
                              void* d_out, int out_size) {
    const float* x   = (const float*)d_in[0];
    const float* gw  = (const float*)d_in[1];
    const float* w13 = (const float*)d_in[2];
    const float* w2  = (const float*)d_in[3];
    float* out = (float*)d_out;

    cudaFuncSetAttribute(gemm1_kernel, cudaFuncAttributeMaxDynamicSharedMemorySize, GEMM_SMEM);
    cudaFuncSetAttribute(gemm2_kernel, cudaFuncAttributeMaxDynamicSharedMemorySize, GEMM_SMEM);

    reset_kernel<<<1, 32>>>();                                                 // launch 0
    prep_kernel<<<PREP_W13 + PREP_W2 + PREP_GATE, 256>>>(w13, w2, x, gw, out); // launch 1
    gemm1_kernel<<<dim3(INTER / 64, CAP / 128, NE), 256, GEMM_SMEM>>>();       // launch 2
    gemm2_kernel<<<dim3(HID / 128, CAP / 128, NE), 256, GEMM_SMEM>>>(out);     // launch 3 (ncu)
}